// round 5
// baseline (speedup 1.0000x reference)
#include <cuda_runtime.h>
#include <cuda_bf16.h>
#include <cstdint>

#define N 4096
#define D 512
#define NITER 10
#define NBS 512          // sinkhorn blocks
#define RPB (N / NBS)    // 8 rows per block
#define QS 8             // reduce-A splits
#define MHAT 4.0f        // safe global LSE shift (sim in [-1,1], |c| small)

// ---------------- device scratch ----------------
__device__ __align__(256) __nv_bfloat16 g_sn[N * D];
__device__ __align__(256) __nv_bfloat16 g_tn[N * D];
__device__ __align__(256) float g_sim[(size_t)N * N];
__device__ __align__(256) float g_r[N];
__device__ __align__(256) float g_c[N];
__device__ __align__(256) float g_part[(size_t)NBS * N];
__device__ __align__(256) float g_p2[(size_t)QS * N];

// ---------------- helpers ----------------
__device__ __forceinline__ uint32_t smem_u32(const void* p) {
    return (uint32_t)__cvta_generic_to_shared(p);
}
// swizzled byte offset into a 128x64B tile (16B chunks, conflict-free)
__device__ __forceinline__ int sw(int row, int kb) {
    return row * 64 + ((((kb >> 4) ^ ((row >> 1) & 3))) << 4) + (kb & 15);
}
__device__ __forceinline__ void ldm_x4(uint32_t& r0, uint32_t& r1, uint32_t& r2,
                                       uint32_t& r3, uint32_t addr) {
    asm volatile("ldmatrix.sync.aligned.m8n8.x4.shared.b16 {%0,%1,%2,%3}, [%4];"
                 : "=r"(r0), "=r"(r1), "=r"(r2), "=r"(r3)
                 : "r"(addr));
}

// ---------------- 1) row L2-normalize fp32 -> bf16 ----------------
__global__ void knorm(const float* __restrict__ src, int which) {
    __nv_bfloat16* dst = which ? g_tn : g_sn;
    int row = blockIdx.x;
    int t = threadIdx.x;  // 128
    const float* p = src + (size_t)row * D;
    float v[4];
    float ss = 0.f;
#pragma unroll
    for (int i = 0; i < 4; i++) { v[i] = p[t + 128 * i]; ss += v[i] * v[i]; }
#pragma unroll
    for (int o = 16; o > 0; o >>= 1) ss += __shfl_xor_sync(0xffffffffu, ss, o);
    __shared__ float red[4];
    if ((t & 31) == 0) red[t >> 5] = ss;
    __syncthreads();
    float inv = rsqrtf(red[0] + red[1] + red[2] + red[3]);
#pragma unroll
    for (int i = 0; i < 4; i++)
        dst[(size_t)row * D + t + 128 * i] = __float2bfloat16(v[i] * inv);
}

// ---------------- 2) bf16 TN GEMM: sim = Sn * Tn^T ----------------
#define BM 128
#define BN 128
#define BK 32
#define KT (D / BK)  // 16
#define STAGES 3

#define LOAD_STAGE(st, kt)                                                          \
    do {                                                                            \
        _Pragma("unroll") for (int q = 0; q < 2; q++) {                             \
            int l = tid + 256 * q;                                                  \
            int rr = l >> 2, cc = l & 3;                                            \
            const void* ga = g_sn + (size_t)(bm * BM + rr) * D + (kt)*BK + cc * 8;  \
            uint32_t da = smem_u32(&sA[st][sw(rr, cc * 16)]);                       \
            asm volatile("cp.async.cg.shared.global [%0], [%1], 16;" ::"r"(da),     \
                         "l"(ga));                                                  \
            const void* gb = g_tn + (size_t)(bn * BN + rr) * D + (kt)*BK + cc * 8;  \
            uint32_t db = smem_u32(&sB[st][sw(rr, cc * 16)]);                       \
            asm volatile("cp.async.cg.shared.global [%0], [%1], 16;" ::"r"(db),     \
                         "l"(gb));                                                  \
        }                                                                           \
        asm volatile("cp.async.commit_group;");                                     \
    } while (0)

__global__ void kgemm() {
    __shared__ __align__(16) char sA[STAGES][128 * 64];
    __shared__ __align__(16) char sB[STAGES][128 * 64];
    int tid = threadIdx.x;  // 256
    int warp = tid >> 5, lane = tid & 31;
    int wm = warp >> 2, wn = warp & 3;  // 2(M) x 4(N) warps, each 64x32
    int g = lane >> 2, tg = lane & 3;
    int lr = lane & 15, lc = lane >> 4;  // ldmatrix addressing
    int bm = blockIdx.y, bn = blockIdx.x;

    float acc[4][4][4];
#pragma unroll
    for (int a = 0; a < 4; a++)
#pragma unroll
        for (int b = 0; b < 4; b++)
#pragma unroll
            for (int c = 0; c < 4; c++) acc[a][b][c] = 0.f;

    LOAD_STAGE(0, 0);
    LOAD_STAGE(1, 1);

    for (int kt = 0; kt < KT; kt++) {
        asm volatile("cp.async.wait_group 1;");
        __syncthreads();
        if (kt + 2 < KT) LOAD_STAGE((kt + 2) % STAGES, kt + 2);
        else asm volatile("cp.async.commit_group;");

        const char* cA = sA[kt % STAGES];
        const char* cB = sB[kt % STAGES];
#pragma unroll
        for (int k16 = 0; k16 < 2; k16++) {
            uint32_t af[4][4], bfr[4][2];
#pragma unroll
            for (int mf = 0; mf < 4; mf++) {
                uint32_t ad =
                    smem_u32(cA + sw(wm * 64 + mf * 16 + lr, k16 * 32 + lc * 16));
                ldm_x4(af[mf][0], af[mf][1], af[mf][2], af[mf][3], ad);
            }
#pragma unroll
            for (int p = 0; p < 2; p++) {
                uint32_t bd =
                    smem_u32(cB + sw(wn * 32 + p * 16 + lr, k16 * 32 + lc * 16));
                uint32_t r0, r1, r2, r3;
                ldm_x4(r0, r1, r2, r3, bd);
                bfr[2 * p][0] = r0;
                bfr[2 * p + 1][0] = r1;
                bfr[2 * p][1] = r2;
                bfr[2 * p + 1][1] = r3;
            }
#pragma unroll
            for (int mf = 0; mf < 4; mf++)
#pragma unroll
                for (int nf = 0; nf < 4; nf++)
                    asm volatile(
                        "mma.sync.aligned.m16n8k16.row.col.f32.bf16.bf16.f32 "
                        "{%0,%1,%2,%3}, {%4,%5,%6,%7}, {%8,%9}, {%0,%1,%2,%3};"
                        : "+f"(acc[mf][nf][0]), "+f"(acc[mf][nf][1]),
                          "+f"(acc[mf][nf][2]), "+f"(acc[mf][nf][3])
                        : "r"(af[mf][0]), "r"(af[mf][1]), "r"(af[mf][2]),
                          "r"(af[mf][3]), "r"(bfr[nf][0]), "r"(bfr[nf][1]));
        }
    }

#pragma unroll
    for (int mf = 0; mf < 4; mf++) {
        int r0 = bm * BM + wm * 64 + mf * 16 + g;
#pragma unroll
        for (int nf = 0; nf < 4; nf++) {
            int col = bn * BN + wn * 32 + nf * 8 + tg * 2;
            *(float2*)&g_sim[(size_t)r0 * N + col] =
                make_float2(acc[mf][nf][0], acc[mf][nf][1]);
            *(float2*)&g_sim[(size_t)(r0 + 8) * N + col] =
                make_float2(acc[mf][nf][2], acc[mf][nf][3]);
        }
    }
}

// ---------------- 3) init c = 0 ----------------
__global__ void kinitc() { g_c[blockIdx.x * 256 + threadIdx.x] = 0.f; }

// ---------------- 4) fused Sinkhorn pass ----------------
// per block: 8 rows (2 at a time). r_i = MHAT + log sum_j exp(sim-c_j-MHAT);
// column partials of exp(sim-c_j-r_i) = v/S accumulated for free.
__global__ void ksink() {
    __shared__ float red[8][2];
    int t = threadIdx.x;  // 256
    int wid = t >> 5, lane = t & 31;
    float cj[16], acc16[16];
#pragma unroll
    for (int kk = 0; kk < 16; kk++) {
        cj[kk] = g_c[t + 256 * kk] + MHAT;
        acc16[kk] = 0.f;
    }
    for (int rb = 0; rb < RPB / 2; rb++) {
        int i0 = blockIdx.x * RPB + rb * 2;
        const float* row0 = g_sim + (size_t)i0 * N;
        const float* row1 = row0 + N;
        float v0[16], v1[16];
        float s0 = 0.f, s1 = 0.f;
#pragma unroll
        for (int kk = 0; kk < 16; kk++) {
            v0[kk] = __expf(row0[t + 256 * kk] - cj[kk]);
            v1[kk] = __expf(row1[t + 256 * kk] - cj[kk]);
            s0 += v0[kk];
            s1 += v1[kk];
        }
#pragma unroll
        for (int o = 16; o > 0; o >>= 1) {
            s0 += __shfl_xor_sync(~0u, s0, o);
            s1 += __shfl_xor_sync(~0u, s1, o);
        }
        if (lane == 0) { red[wid][0] = s0; red[wid][1] = s1; }
        __syncthreads();
        float S0 = 0.f, S1 = 0.f;
#pragma unroll
        for (int w = 0; w < 8; w++) { S0 += red[w][0]; S1 += red[w][1]; }
        __syncthreads();
        if (t == 0) {
            g_r[i0] = MHAT + __logf(S0);
            g_r[i0 + 1] = MHAT + __logf(S1);
        }
        float is0 = 1.0f / S0, is1 = 1.0f / S1;
#pragma unroll
        for (int kk = 0; kk < 16; kk++)
            acc16[kk] += v0[kk] * is0 + v1[kk] * is1;
    }
#pragma unroll
    for (int kk = 0; kk < 16; kk++)
        g_part[(size_t)blockIdx.x * N + t + 256 * kk] = acc16[kk];
}

// ---------------- 5a) partial combine (coalesced) ----------------
__global__ void kreduceA() {
    int gt = blockIdx.x * 256 + threadIdx.x;  // QS*N threads
    int j = gt & (N - 1);
    int q = gt >> 12;
    float s = 0.f;
#pragma unroll 8
    for (int b = 0; b < NBS / QS; b++)
        s += g_part[(size_t)(q * (NBS / QS) + b) * N + j];
    g_p2[(size_t)q * N + j] = s;
}

// ---------------- 5b) final combine: c_j += log(sum) ----------------
__global__ void kreduceB() {
    int j = blockIdx.x * 256 + threadIdx.x;  // N threads
    float s = 0.f;
#pragma unroll
    for (int q = 0; q < QS; q++) s += g_p2[(size_t)q * N + j];
    g_c[j] += __logf(s);
}

// ---------------- 6) output: exp(sim - r_i - c_j) ----------------
__global__ void kfinal(float* __restrict__ out) {
    int i = blockIdx.x;
    float ri = g_r[i];
    const float4* srow = (const float4*)(g_sim + (size_t)i * N);
    const float4* c4 = (const float4*)g_c;
    float4* orow = (float4*)(out + (size_t)i * N);
    for (int q = threadIdx.x; q < N / 4; q += 256) {
        float4 sv = srow[q];
        float4 cv = c4[q];
        float4 o;
        o.x = __expf(sv.x - ri - cv.x);
        o.y = __expf(sv.y - ri - cv.y);
        o.z = __expf(sv.z - ri - cv.z);
        o.w = __expf(sv.w - ri - cv.w);
        orow[q] = o;
    }
}

// ---------------- launch ----------------
extern "C" void kernel_launch(void* const* d_in, const int* in_sizes, int n_in,
                              void* d_out, int out_size) {
    const float* hs = (const float*)d_in[0];
    const float* ht = (const float*)d_in[1];
    float* out = (float*)d_out;

    knorm<<<N, 128>>>(hs, 0);
    knorm<<<N, 128>>>(ht, 1);
    kinitc<<<N / 256, 256>>>();
    kgemm<<<dim3(N / BN, N / BM), 256>>>();
    for (int it = 0; it < NITER; it++) {
        ksink<<<NBS, 256>>>();
        kreduceA<<<QS * N / 256, 256>>>();
        kreduceB<<<N / 256, 256>>>();
    }
    kfinal<<<N, 256>>>(out);
}